// round 13
// baseline (speedup 1.0000x reference)
#include <cuda_runtime.h>
#include <cstdint>
#include <cstddef>

#define NN 4096
typedef unsigned long long ull;
typedef unsigned int uint32;

__device__ unsigned short d_gbfT[256 * NN];  // bf16 g transposed [feat][node]
__device__ float d_lpack[NN * 12];
__device__ float4 d_rp4[NN * 4];             // {sr, exp(sr), exp(.2sr), 0}
__device__ unsigned d_adjT[128 * NN * 2];    // adjacency bits, tile-major
__device__ float d_hattT[256 * NN];
__device__ float d_part[256 * 256];
__device__ float d_W1T[256 * 256];
__device__ float d_W2T[256 * 256];
__device__ float d_WembT[128 * 256];
__device__ float d_nodesT[128 * NN];

__device__ __forceinline__ ull pack2(float x) { ull r; asm("mov.b64 %0, {%1, %1};" : "=l"(r) : "f"(x)); return r; }
__device__ __forceinline__ ull fma2(ull a, ull b, ull c) { ull d; asm("fma.rn.f32x2 %0, %1, %2, %3;" : "=l"(d) : "l"(a), "l"(b), "l"(c)); return d; }
__device__ __forceinline__ float2 unpack2(ull v) { float2 r; asm("mov.b64 {%0, %1}, %2;" : "=f"(r.x), "=f"(r.y) : "l"(v)); return r; }
__device__ __forceinline__ ull dll(double v) { return __double_as_longlong(v); }
__device__ __forceinline__ void cpa16(void* dst, const void* src) {
    unsigned s = (unsigned)__cvta_generic_to_shared(dst);
    asm volatile("cp.async.cg.shared.global [%0], [%1], 16;" ::"r"(s), "l"(src));
}
__device__ __forceinline__ void cpa8(void* dst, const void* src) {
    unsigned s = (unsigned)__cvta_generic_to_shared(dst);
    asm volatile("cp.async.ca.shared.global [%0], [%1], 8;" ::"r"(s), "l"(src));
}
__device__ __forceinline__ unsigned bf2(float lo, float hi) {
    unsigned r; asm("cvt.rn.bf16x2.f32 %0, %1, %2;" : "=r"(r) : "f"(hi), "f"(lo)); return r;
}
__device__ __forceinline__ uint32 smem_u32(const void* p) {
    uint32 a; asm("{ .reg .u64 t; cvta.to.shared.u64 t, %1; cvt.u32.u64 %0, t; }" : "=r"(a) : "l"(p)); return a;
}
#define CPA_COMMIT() asm volatile("cp.async.commit_group;" ::: "memory")
#define CPA_WAIT1() asm volatile("cp.async.wait_group 1;" ::: "memory")
#define CPA_WAIT0() asm volatile("cp.async.wait_group 0;" ::: "memory")

__device__ __forceinline__ void ldmx4(uint32* r, uint32 addr) {
    asm volatile("ldmatrix.sync.aligned.m8n8.x4.shared.b16 {%0,%1,%2,%3}, [%4];"
                 : "=r"(r[0]), "=r"(r[1]), "=r"(r[2]), "=r"(r[3]) : "r"(addr));
}
__device__ __forceinline__ void mma_bf16(float* c, uint32 a0, uint32 a1, uint32 a2, uint32 a3,
                                         uint32 b0, uint32 b1) {
    asm volatile("mma.sync.aligned.m16n8k16.row.col.f32.bf16.bf16.f32 "
                 "{%0,%1,%2,%3},{%4,%5,%6,%7},{%8,%9},{%0,%1,%2,%3};"
                 : "+f"(c[0]), "+f"(c[1]), "+f"(c[2]), "+f"(c[3])
                 : "r"(a0), "r"(a1), "r"(a2), "r"(a3), "r"(b0), "r"(b1));
}

// ---------------- prep (R8 three-kernel form) ----------------
__global__ __launch_bounds__(256) void k_prep(const float* __restrict__ We1, const float* __restrict__ We2,
                                              const float* __restrict__ Wemb) {
    int i = blockIdx.x * 256 + threadIdx.x;
    if (i < 65536) { int k = i >> 8, c = i & 255; d_W1T[i] = We1[c * 256 + k]; }
    else if (i < 131072) { int j = i - 65536, k = j >> 8, c = j & 255; d_W2T[j] = We2[c * 256 + k]; }
    else { int j = i - 131072, k = j >> 8, c = j & 255; d_WembT[j] = Wemb[c * 128 + k]; }
}
__global__ void k_tnodes(const float* __restrict__ nodes) {
    __shared__ float tile[32][33];
    const int bx = blockIdx.x, by = blockIdx.y, tx = threadIdx.x, ty = threadIdx.y;
#pragma unroll
    for (int q = 0; q < 4; q++)
        tile[ty + 8 * q][tx] = nodes[(size_t)(bx * 32 + ty + 8 * q) * 128 + by * 32 + tx];
    __syncthreads();
#pragma unroll
    for (int q = 0; q < 4; q++)
        d_nodesT[(size_t)(by * 32 + ty + 8 * q) * 4096 + bx * 32 + tx] = tile[tx][ty + 8 * q];
}
__global__ __launch_bounds__(256) void k_adjpack(const int* __restrict__ adj) {
    int wg = (blockIdx.x * 256 + threadIdx.x) >> 5, lane = threadIdx.x & 31;
    unsigned v = (adj[(size_t)wg * 32 + lane] != 0) ? 1u : 0u;
    unsigned word = __ballot_sync(0xFFFFFFFFu, v);
    if (lane == 0) {
        int node = wg >> 7, w = wg & 127;
        d_adjT[(size_t)((w >> 1) * NN + node) * 2 + (w & 1)] = word;
    }
}

// ---------------- K1: embed + fused score packs (R8, unchanged) ----------------
__global__ __launch_bounds__(256) void k_embed(const float* __restrict__ Watt) {
    __shared__ float sA[128 * 32];
    __shared__ float sRed[4096];
    const int tid = threadIdx.x, bi = blockIdx.x;
#pragma unroll
    for (int c = 0; c < 4; c++) {
        int L = tid + c * 256, k = L >> 3, q = L & 7;
        cpa16(sA + k * 32 + q * 4, d_nodesT + (size_t)k * 4096 + bi * 32 + q * 4);
    }
    CPA_COMMIT();
    const int fg = tid & 63, ig = tid >> 6;
    const int rowb = bi * 32 + ig * 8, colb = fg * 4;
    ull w01[2][8], w23[2][8];
#pragma unroll
    for (int u = 0; u < 8; u++) {
        double2 wd = *(const double2*)(d_WembT + u * 256 + colb);
        w01[0][u] = dll(wd.x); w23[0][u] = dll(wd.y);
    }
    CPA_WAIT0();
    __syncthreads();
    ull acc[16];
#pragma unroll
    for (int q = 0; q < 16; q++) acc[q] = 0ull;
#pragma unroll 1
    for (int k0 = 0; k0 < 128; k0 += 8) {
        int cb = (k0 >> 3) & 1, nb = cb ^ 1;
        if (k0 < 120) {
#pragma unroll
            for (int u = 0; u < 8; u++) {
                double2 wd = *(const double2*)(d_WembT + (k0 + 8 + u) * 256 + colb);
                w01[nb][u] = dll(wd.x); w23[nb][u] = dll(wd.y);
            }
        }
#pragma unroll
        for (int u = 0; u < 8; u++) {
            const float* ar = sA + (k0 + u) * 32 + ig * 8;
#pragma unroll
            for (int r = 0; r < 8; r++) {
                ull p = pack2(ar[r]);
                acc[r * 2] = fma2(p, w01[cb][u], acc[r * 2]);
                acc[r * 2 + 1] = fma2(p, w23[cb][u], acc[r * 2 + 1]);
            }
        }
    }
    float z[8][4];
#pragma unroll
    for (int r = 0; r < 8; r++) {
        float2 u0 = unpack2(acc[r * 2]), u1 = unpack2(acc[r * 2 + 1]);
        z[r][0] = u0.x; z[r][1] = u0.y; z[r][2] = u1.x; z[r][3] = u1.y;
    }
#pragma unroll
    for (int cc = 0; cc < 4; cc++) {
        uint4 q = make_uint4(bf2(z[0][cc], z[1][cc]), bf2(z[2][cc], z[3][cc]),
                             bf2(z[4][cc], z[5][cc]), bf2(z[6][cc], z[7][cc]));
        *(uint4*)((char*)d_gbfT + ((size_t)(colb + cc) * 4096 + rowb) * 2) = q;
    }
    const int h = fg >> 4, fi = fg & 15;
    float4 al = *(const float4*)(Watt + (colb & 63));
    float4 ar4 = *(const float4*)(Watt + 64 + (colb & 63));
#pragma unroll
    for (int r = 0; r < 8; r++) {
        float slp = z[r][0] * al.x + z[r][1] * al.y + z[r][2] * al.z + z[r][3] * al.w;
        float srp = z[r][0] * ar4.x + z[r][1] * ar4.y + z[r][2] * ar4.z + z[r][3] * ar4.w;
        int ri = ig * 8 + r;
        sRed[((ri * 4 + h) * 2 + 0) * 16 + fi] = slp;
        sRed[((ri * 4 + h) * 2 + 1) * 16 + fi] = srp;
    }
    __syncthreads();
    if (tid < 128) {
        int ri = tid >> 2, hh = tid & 3;
        float sl = 0.f, sr = 0.f;
#pragma unroll
        for (int q = 0; q < 16; q++) {
            sl += sRed[((ri * 4 + hh) * 2 + 0) * 16 + q];
            sr += sRed[((ri * 4 + hh) * 2 + 1) * 16 + q];
        }
        int gi = bi * 32 + ri;
        d_lpack[gi * 12 + hh] = sl;
        d_lpack[gi * 12 + 4 + hh] = expf(sl);
        d_lpack[gi * 12 + 8 + hh] = expf(0.2f * sl);
        d_rp4[gi * 4 + hh] = make_float4(sr, expf(sr), expf(0.2f * sr), 0.f);
    }
}

// ---------------- K2: HMMA attention (R8, unchanged) ----------------
#define G_OFF 0
#define RP_OFF 98304
#define ADJ_OFF 113664
#define DEN_OFF 114432
#define INV_OFF 114944
#define K2_SMEM 115456

__device__ __forceinline__ void issue_tile(int t, int slot, int tid, int bi, char* sb) {
    char* Gd = sb + G_OFF + slot * 32768;
    const char* gsrc = (const char*)d_gbfT + (size_t)t * 128;
#pragma unroll
    for (int kk = 0; kk < 8; kk++) {
        int L = tid + kk * 256, row = L >> 3, c = L & 7;
        cpa16(Gd + row * 128 + ((c ^ (row & 7)) << 4), gsrc + (size_t)row * 8192 + c * 16);
    }
    int j = tid >> 2, hh = tid & 3;
    cpa16(sb + RP_OFF + slot * 5120 + j * 80 + hh * 16, d_rp4 + t * 256 + tid);
    if (tid < 32)
        cpa8(sb + ADJ_OFF + slot * 256 + tid * 8, d_adjT + (size_t)(t * NN + bi * 32 + tid) * 2);
}

__global__ __launch_bounds__(256, 1) void k_attn() {
    extern __shared__ char sb[];
    const uint32 sb32 = smem_u32(sb);
    const int tid = threadIdx.x, bi = blockIdx.x;
    const int lane = tid & 31, wid = tid >> 5;
    const int h = wid >> 1, mh = wid & 1;
    const int i4 = lane >> 2, q = lane & 3, jq = q << 1;
    const int r0 = mh * 16 + i4;

    float sl[2], e1[2], e2[2];
#pragma unroll
    for (int r = 0; r < 2; r++) {
        int gi = bi * 32 + r0 + 8 * r;
        sl[r] = d_lpack[gi * 12 + h];
        e1[r] = d_lpack[gi * 12 + 4 + h];
        e2[r] = d_lpack[gi * 12 + 8 + h];
    }
    float C[8][4];
#pragma unroll
    for (int nf = 0; nf < 8; nf++)
#pragma unroll
        for (int qq = 0; qq < 4; qq++) C[nf][qq] = 0.f;
    float dsum[2] = {0.f, 0.f};

    issue_tile(0, 0, tid, bi, sb); CPA_COMMIT();
    issue_tile(1, 1, tid, bi, sb); CPA_COMMIT();

#pragma unroll 1
    for (int t = 0; t < 64; t++) {
        if (t < 63) CPA_WAIT1(); else CPA_WAIT0();
        __syncthreads();
        if (t + 2 < 64) { issue_tile(t + 2, (t + 2) % 3, tid, bi, sb); CPA_COMMIT(); }
        const int slot = t % 3;

        uint32 B[8][8];
        {
            const uint32 gb32 = sb32 + G_OFF + slot * 32768;
            const int fr = h * 64 + (lane & 7), c0 = lane >> 3;
#pragma unroll
            for (int nf = 0; nf < 8; nf++) {
                int f = fr + nf * 8;
                uint32 base = gb32 + f * 128;
                ldmx4(&B[nf][0], base + ((c0 ^ (f & 7)) << 4));
                ldmx4(&B[nf][4], base + (((c0 + 4) ^ (f & 7)) << 4));
            }
        }
        uint32 A[2][8];
        {
            const uint32* sadj = (const uint32*)(sb + ADJ_OFF + slot * 256);
            uint32 aw[2][2];
#pragma unroll
            for (int r = 0; r < 2; r++) {
                aw[r][0] = sadj[(r0 + 8 * r) * 2];
                aw[r][1] = sadj[(r0 + 8 * r) * 2 + 1];
            }
            const char* rpb = sb + RP_OFF + slot * 5120 + h * 16;
#pragma unroll
            for (int c = 0; c < 8; c++) {
                int j0 = jq + (c << 3);
                float4 p0 = *(const float4*)(rpb + j0 * 80);
                float4 p1 = *(const float4*)(rpb + j0 * 80 + 80);
                int half = c >> 2, sh = j0 & 31;
#pragma unroll
                for (int r = 0; r < 2; r++) {
                    float w0 = (sl[r] + p0.x >= 0.f) ? e1[r] * p0.y : e2[r] * p0.z;
                    float w1 = (sl[r] + p1.x >= 0.f) ? e1[r] * p1.y : e2[r] * p1.z;
                    w0 = ((aw[r][half] >> sh) & 1u) ? w0 : 0.f;
                    w1 = ((aw[r][half] >> (sh + 1)) & 1u) ? w1 : 0.f;
                    dsum[r] += w0 + w1;
                    A[r][c] = bf2(w0, w1);
                }
            }
        }
#pragma unroll
        for (int s = 0; s < 4; s++)
#pragma unroll
            for (int nf = 0; nf < 8; nf++)
                mma_bf16(C[nf], A[0][2 * s], A[1][2 * s], A[0][2 * s + 1], A[1][2 * s + 1],
                         B[nf][2 * s], B[nf][2 * s + 1]);
    }

#pragma unroll
    for (int r = 0; r < 2; r++) {
        dsum[r] += __shfl_xor_sync(0xFFFFFFFFu, dsum[r], 1);
        dsum[r] += __shfl_xor_sync(0xFFFFFFFFu, dsum[r], 2);
    }
    float* den = (float*)(sb + DEN_OFF);
    if ((lane & 3) == 0) {
        den[h * 32 + r0] = dsum[0];
        den[h * 32 + r0 + 8] = dsum[1];
    }
    __syncthreads();
    float* inv = (float*)(sb + INV_OFF);
    if (tid < 128) inv[tid] = 1.f / den[tid];
    __syncthreads();
    float* sOut = (float*)(sb + G_OFF);
    {
        float s0 = inv[h * 32 + r0], s8 = inv[h * 32 + r0 + 8];
#pragma unroll
        for (int nf = 0; nf < 8; nf++) {
            int f0 = h * 64 + nf * 8 + jq;
            float* qp = sOut + r0 * 264 + f0;
            qp[0] = C[nf][0] * s0; qp[1] = C[nf][1] * s0;
            float* q8 = sOut + (r0 + 8) * 264 + f0;
            q8[0] = C[nf][2] * s8; q8[1] = C[nf][3] * s8;
        }
    }
    __syncthreads();
#pragma unroll
    for (int n4 = 0; n4 < 8; n4++) {
        float4 v;
        v.x = sOut[(n4 * 4 + 0) * 264 + tid];
        v.y = sOut[(n4 * 4 + 1) * 264 + tid];
        v.z = sOut[(n4 * 4 + 2) * 264 + tid];
        v.w = sOut[(n4 * 4 + 3) * 264 + tid];
        *(float4*)(d_hattT + (size_t)tid * 4096 + bi * 32 + n4 * 4) = v;
    }
}

// ---------------- K3: MLP + partial pool — grid 256, 16 rows/block ----------------
// dyn smem: phase1 [k*16+row] 4096 f; phase2 [hid*20+row] 5120 f -> alloc 5120 f = 20480 B
__global__ __launch_bounds__(256) void k_mlp(const float* __restrict__ b1, const float* __restrict__ b2) {
    extern __shared__ float sm[];
    __shared__ float sPart[1024];
    const int tid = threadIdx.x, bi = blockIdx.x;
    const int fg = tid & 63, ig = tid >> 6;
    const int colb = fg * 4;
    // stage Hatt tile: 256 k x 16 floats
#pragma unroll
    for (int c = 0; c < 4; c++) {
        int L = tid + c * 256, k = L >> 2, qq = L & 3;
        cpa16(sm + k * 16 + qq * 4, d_hattT + (size_t)k * 4096 + bi * 16 + qq * 4);
    }
    CPA_COMMIT();
    ull w01[2][8], w23[2][8];
#pragma unroll
    for (int u = 0; u < 8; u++) {
        double2 wd = *(const double2*)(d_W1T + u * 256 + colb);
        w01[0][u] = dll(wd.x); w23[0][u] = dll(wd.y);
    }
    CPA_WAIT0();
    __syncthreads();
    ull acc[8];
#pragma unroll
    for (int qq = 0; qq < 8; qq++) acc[qq] = 0ull;
#pragma unroll 1
    for (int k0 = 0; k0 < 256; k0 += 8) {
        int cb = (k0 >> 3) & 1, nb = cb ^ 1;
        if (k0 < 248) {
#pragma unroll
            for (int u = 0; u < 8; u++) {
                double2 wd = *(const double2*)(d_W1T + (k0 + 8 + u) * 256 + colb);
                w01[nb][u] = dll(wd.x); w23[nb][u] = dll(wd.y);
            }
        }
#pragma unroll
        for (int u = 0; u < 8; u++) {
            float4 av = *(const float4*)(sm + (k0 + u) * 16 + ig * 4);
            ull p;
            p = pack2(av.x); acc[0] = fma2(p, w01[cb][u], acc[0]); acc[1] = fma2(p, w23[cb][u], acc[1]);
            p = pack2(av.y); acc[2] = fma2(p, w01[cb][u], acc[2]); acc[3] = fma2(p, w23[cb][u], acc[3]);
            p = pack2(av.z); acc[4] = fma2(p, w01[cb][u], acc[4]); acc[5] = fma2(p, w23[cb][u], acc[5]);
            p = pack2(av.w); acc[6] = fma2(p, w01[cb][u], acc[6]); acc[7] = fma2(p, w23[cb][u], acc[7]);
        }
    }
    float4 bb = *(const float4*)(b1 + colb);
    float zz[4][4];
#pragma unroll
    for (int r = 0; r < 4; r++) {
        float2 u0 = unpack2(acc[r * 2]), u1 = unpack2(acc[r * 2 + 1]);
        zz[r][0] = fmaxf(u0.x + bb.x, 0.f); zz[r][1] = fmaxf(u0.y + bb.y, 0.f);
        zz[r][2] = fmaxf(u1.x + bb.z, 0.f); zz[r][3] = fmaxf(u1.y + bb.w, 0.f);
    }
    __syncthreads();
    // re-lay layer-1 output: [hid][row], stride 20 (16B-aligned rows)
#pragma unroll
    for (int cc = 0; cc < 4; cc++)
#pragma unroll
        for (int r = 0; r < 4; r++)
            sm[(colb + cc) * 20 + ig * 4 + r] = zz[r][cc];
#pragma unroll
    for (int u = 0; u < 8; u++) {
        double2 wd = *(const double2*)(d_W2T + u * 256 + colb);
        w01[0][u] = dll(wd.x); w23[0][u] = dll(wd.y);
    }
    __syncthreads();
#pragma unroll
    for (int qq = 0; qq < 8; qq++) acc[qq] = 0ull;
#pragma unroll 1
    for (int k0 = 0; k0 < 256; k0 += 8) {
        int cb = (k0 >> 3) & 1, nb = cb ^ 1;
        if (k0 < 248) {
#pragma unroll
            for (int u = 0; u < 8; u++) {
                double2 wd = *(const double2*)(d_W2T + (k0 + 8 + u) * 256 + colb);
                w01[nb][u] = dll(wd.x); w23[nb][u] = dll(wd.y);
            }
        }
#pragma unroll
        for (int u = 0; u < 8; u++) {
            float4 av = *(const float4*)(sm + (k0 + u) * 20 + ig * 4);
            ull p;
            p = pack2(av.x); acc[0] = fma2(p, w01[cb][u], acc[0]); acc[1] = fma2(p, w23[cb][u], acc[1]);
            p = pack2(av.y); acc[2] = fma2(p, w01[cb][u], acc[2]); acc[3] = fma2(p, w23[cb][u], acc[3]);
            p = pack2(av.z); acc[4] = fma2(p, w01[cb][u], acc[4]); acc[5] = fma2(p, w23[cb][u], acc[5]);
            p = pack2(av.w); acc[6] = fma2(p, w01[cb][u], acc[6]); acc[7] = fma2(p, w23[cb][u], acc[7]);
        }
    }
    float4 b2v = *(const float4*)(b2 + colb);
    float pc0 = 4.f * b2v.x, pc1 = 4.f * b2v.y, pc2 = 4.f * b2v.z, pc3 = 4.f * b2v.w;
#pragma unroll
    for (int r = 0; r < 4; r++) {
        float2 u0 = unpack2(acc[r * 2]), u1 = unpack2(acc[r * 2 + 1]);
        pc0 += u0.x; pc1 += u0.y; pc2 += u1.x; pc3 += u1.y;
    }
    *(float4*)(sPart + ig * 256 + colb) = make_float4(pc0, pc1, pc2, pc3);
    __syncthreads();
    d_part[bi * 256 + tid] = sPart[tid] + sPart[256 + tid] + sPart[512 + tid] + sPart[768 + tid];
}

// ---------------- K4 ----------------
__global__ __launch_bounds__(256) void k_final(const float* __restrict__ Wd1, const float* __restrict__ bd1,
                                               const float* __restrict__ Wd2, const float* __restrict__ bd2,
                                               float* __restrict__ out) {
    __shared__ float pooled[256];
    __shared__ float red[256];
    const int o = threadIdx.x;
    float p = 0.f;
    for (int b = 0; b < 256; b++) p += d_part[b * 256 + o];
    pooled[o] = p;
    __syncthreads();
    float accv = 0.f;
    const float* w = Wd1 + o * 256;
#pragma unroll 4
    for (int k = 0; k < 256; k++) accv += w[k] * pooled[k];
    red[o] = fmaxf(accv + bd1[o], 0.f) * Wd2[o];
    __syncthreads();
    for (int s = 128; s > 0; s >>= 1) {
        if (o < s) red[o] += red[o + s];
        __syncthreads();
    }
    if (o == 0) out[0] = red[0] + bd2[0];
}

extern "C" void kernel_launch(void* const* d_in, const int* in_sizes, int n_in,
                              void* d_out, int out_size) {
    const float* nodes = (const float*)d_in[0];
    const int* adj = (const int*)d_in[1];
    const float* Wemb = (const float*)d_in[2];
    const float* Watt = (const float*)d_in[3];
    const float* We1 = (const float*)d_in[4];
    const float* b1 = (const float*)d_in[5];
    const float* We2 = (const float*)d_in[6];
    const float* b2 = (const float*)d_in[7];
    const float* Wd1 = (const float*)d_in[8];
    const float* bd1 = (const float*)d_in[9];
    const float* Wd2 = (const float*)d_in[10];
    const float* bd2 = (const float*)d_in[11];
    float* out = (float*)d_out;

    cudaFuncSetAttribute(k_attn, cudaFuncAttributeMaxDynamicSharedMemorySize, K2_SMEM);

    k_prep<<<640, 256>>>(We1, We2, Wemb);
    k_tnodes<<<dim3(128, 4), dim3(32, 8)>>>(nodes);
    k_adjpack<<<65536, 256>>>(adj);
    k_embed<<<128, 256>>>(Watt);
    k_attn<<<128, 256, K2_SMEM>>>();
    k_mlp<<<256, 256, 20480>>>(b1, b2);
    k_final<<<1, 256>>>(Wd1, bd1, Wd2, bd2, out);
}

// round 14
// speedup vs baseline: 1.3628x; 1.3628x over previous
#include <cuda_runtime.h>
#include <cstdint>
#include <cstddef>

#define NN 4096
typedef unsigned long long ull;
typedef unsigned int uint32;

__device__ unsigned short d_gbfT[256 * NN];  // bf16 g transposed [feat][node]
__device__ float d_lpack[NN * 12];
__device__ float4 d_rp4[NN * 4];             // {sr, exp(sr), exp(.2sr), 0}
__device__ unsigned d_adjT[128 * NN * 2];    // adjacency bits, tile-major
__device__ float d_hattT[256 * NN];
__device__ float d_part[128 * 256];
__device__ float d_W1T[256 * 256];
__device__ float d_W2T[256 * 256];
__device__ float d_WembT[128 * 256];
__device__ float d_nodesT[128 * NN];

__device__ __forceinline__ ull pack2(float x) { ull r; asm("mov.b64 %0, {%1, %1};" : "=l"(r) : "f"(x)); return r; }
__device__ __forceinline__ ull fma2(ull a, ull b, ull c) { ull d; asm("fma.rn.f32x2 %0, %1, %2, %3;" : "=l"(d) : "l"(a), "l"(b), "l"(c)); return d; }
__device__ __forceinline__ float2 unpack2(ull v) { float2 r; asm("mov.b64 {%0, %1}, %2;" : "=f"(r.x), "=f"(r.y) : "l"(v)); return r; }
__device__ __forceinline__ ull dll(double v) { return __double_as_longlong(v); }
__device__ __forceinline__ void cpa16(void* dst, const void* src) {
    unsigned s = (unsigned)__cvta_generic_to_shared(dst);
    asm volatile("cp.async.cg.shared.global [%0], [%1], 16;" ::"r"(s), "l"(src));
}
__device__ __forceinline__ void cpa8(void* dst, const void* src) {
    unsigned s = (unsigned)__cvta_generic_to_shared(dst);
    asm volatile("cp.async.ca.shared.global [%0], [%1], 8;" ::"r"(s), "l"(src));
}
__device__ __forceinline__ unsigned bf2(float lo, float hi) {
    unsigned r; asm("cvt.rn.bf16x2.f32 %0, %1, %2;" : "=r"(r) : "f"(hi), "f"(lo)); return r;
}
__device__ __forceinline__ uint32 smem_u32(const void* p) {
    uint32 a; asm("{ .reg .u64 t; cvta.to.shared.u64 t, %1; cvt.u32.u64 %0, t; }" : "=r"(a) : "l"(p)); return a;
}
#define CPA_COMMIT() asm volatile("cp.async.commit_group;" ::: "memory")
#define CPA_WAIT1() asm volatile("cp.async.wait_group 1;" ::: "memory")
#define CPA_WAIT0() asm volatile("cp.async.wait_group 0;" ::: "memory")

__device__ __forceinline__ void ldmx4(uint32* r, uint32 addr) {
    asm volatile("ldmatrix.sync.aligned.m8n8.x4.shared.b16 {%0,%1,%2,%3}, [%4];"
                 : "=r"(r[0]), "=r"(r[1]), "=r"(r[2]), "=r"(r[3]) : "r"(addr));
}
__device__ __forceinline__ void mma_bf16(float* c, uint32 a0, uint32 a1, uint32 a2, uint32 a3,
                                         uint32 b0, uint32 b1) {
    asm volatile("mma.sync.aligned.m16n8k16.row.col.f32.bf16.bf16.f32 "
                 "{%0,%1,%2,%3},{%4,%5,%6,%7},{%8,%9},{%0,%1,%2,%3};"
                 : "+f"(c[0]), "+f"(c[1]), "+f"(c[2]), "+f"(c[3])
                 : "r"(a0), "r"(a1), "r"(a2), "r"(a3), "r"(b0), "r"(b1));
}

// ---------------- prep: weight transposes ----------------
__global__ __launch_bounds__(256) void k_prep(const float* __restrict__ We1, const float* __restrict__ We2,
                                              const float* __restrict__ Wemb) {
    int i = blockIdx.x * 256 + threadIdx.x;  // 163840
    if (i < 65536) { int k = i >> 8, c = i & 255; d_W1T[i] = We1[c * 256 + k]; }
    else if (i < 131072) { int j = i - 65536, k = j >> 8, c = j & 255; d_W2T[j] = We2[c * 256 + k]; }
    else { int j = i - 131072, k = j >> 8, c = j & 255; d_WembT[j] = Wemb[c * 128 + k]; }
}
__global__ void k_tnodes(const float* __restrict__ nodes) {
    __shared__ float tile[32][33];
    const int bx = blockIdx.x, by = blockIdx.y, tx = threadIdx.x, ty = threadIdx.y;
#pragma unroll
    for (int q = 0; q < 4; q++)
        tile[ty + 8 * q][tx] = nodes[(size_t)(bx * 32 + ty + 8 * q) * 128 + by * 32 + tx];
    __syncthreads();
#pragma unroll
    for (int q = 0; q < 4; q++)
        d_nodesT[(size_t)(by * 32 + ty + 8 * q) * 4096 + bx * 32 + tx] = tile[tx][ty + 8 * q];
}
__global__ __launch_bounds__(256) void k_adjpack(const int* __restrict__ adj) {
    int wg = (blockIdx.x * 256 + threadIdx.x) >> 5, lane = threadIdx.x & 31;
    unsigned v = (adj[(size_t)wg * 32 + lane] != 0) ? 1u : 0u;
    unsigned word = __ballot_sync(0xFFFFFFFFu, v);
    if (lane == 0) {
        int node = wg >> 7, w = wg & 127;
        d_adjT[(size_t)((w >> 1) * NN + node) * 2 + (w & 1)] = word;
    }
}

// ---------------- K1: embed + fused score packs (smem-staged, prefetched) ----------------
__global__ __launch_bounds__(256) void k_embed(const float* __restrict__ Watt) {
    __shared__ float sA[128 * 32];   // [k][row] 16KB
    __shared__ float sRed[4096];
    const int tid = threadIdx.x, bi = blockIdx.x;
    // stage node tile: 128 k-rows x 32 floats
#pragma unroll
    for (int c = 0; c < 4; c++) {
        int L = tid + c * 256, k = L >> 3, q = L & 7;
        cpa16(sA + k * 32 + q * 4, d_nodesT + (size_t)k * 4096 + bi * 32 + q * 4);
    }
    CPA_COMMIT(); CPA_WAIT0();
    __syncthreads();

    const int fg = tid & 63, ig = tid >> 6;
    const int rowb = bi * 32 + ig * 8, colb = fg * 4;
    ull acc[16];
#pragma unroll
    for (int q = 0; q < 16; q++) acc[q] = 0ull;
#pragma unroll 1
    for (int k0 = 0; k0 < 128; k0 += 8) {
        ull w01[8], w23[8];
#pragma unroll
        for (int u = 0; u < 8; u++) {
            double2 wd = *(const double2*)(d_WembT + (k0 + u) * 256 + colb);
            w01[u] = dll(wd.x); w23[u] = dll(wd.y);
        }
#pragma unroll
        for (int u = 0; u < 8; u++) {
            const float* ar = sA + (k0 + u) * 32 + ig * 8;
#pragma unroll
            for (int r = 0; r < 8; r++) {
                ull p = pack2(ar[r]);
                acc[r * 2] = fma2(p, w01[u], acc[r * 2]);
                acc[r * 2 + 1] = fma2(p, w23[u], acc[r * 2 + 1]);
            }
        }
    }
    float z[8][4];
#pragma unroll
    for (int r = 0; r < 8; r++) {
        float2 u0 = unpack2(acc[r * 2]), u1 = unpack2(acc[r * 2 + 1]);
        z[r][0] = u0.x; z[r][1] = u0.y; z[r][2] = u1.x; z[r][3] = u1.y;
    }
#pragma unroll
    for (int cc = 0; cc < 4; cc++) {
        uint4 q = make_uint4(bf2(z[0][cc], z[1][cc]), bf2(z[2][cc], z[3][cc]),
                             bf2(z[4][cc], z[5][cc]), bf2(z[6][cc], z[7][cc]));
        *(uint4*)((char*)d_gbfT + ((size_t)(colb + cc) * 4096 + rowb) * 2) = q;
    }
    // fused attention-score partials
    const int h = fg >> 4, fi = fg & 15;
    float4 al = *(const float4*)(Watt + (colb & 63));
    float4 ar4 = *(const float4*)(Watt + 64 + (colb & 63));
#pragma unroll
    for (int r = 0; r < 8; r++) {
        float slp = z[r][0] * al.x + z[r][1] * al.y + z[r][2] * al.z + z[r][3] * al.w;
        float srp = z[r][0] * ar4.x + z[r][1] * ar4.y + z[r][2] * ar4.z + z[r][3] * ar4.w;
        int ri = ig * 8 + r;
        sRed[((ri * 4 + h) * 2 + 0) * 16 + fi] = slp;
        sRed[((ri * 4 + h) * 2 + 1) * 16 + fi] = srp;
    }
    __syncthreads();
    if (tid < 128) {
        int ri = tid >> 2, hh = tid & 3;
        float sl = 0.f, sr = 0.f;
#pragma unroll
        for (int q = 0; q < 16; q++) {
            sl += sRed[((ri * 4 + hh) * 2 + 0) * 16 + q];
            sr += sRed[((ri * 4 + hh) * 2 + 1) * 16 + q];
        }
        int gi = bi * 32 + ri;
        d_lpack[gi * 12 + hh] = sl;
        d_lpack[gi * 12 + 4 + hh] = expf(sl);
        d_lpack[gi * 12 + 8 + hh] = expf(0.2f * sl);
        d_rp4[gi * 4 + hh] = make_float4(sr, expf(sr), expf(0.2f * sr), 0.f);
    }
}

// ---------------- K2: HMMA attention (unchanged from R7) ----------------
#define G_OFF 0
#define RP_OFF 98304
#define ADJ_OFF 113664
#define DEN_OFF 114432
#define INV_OFF 114944
#define K2_SMEM 115456

__device__ __forceinline__ void issue_tile(int t, int slot, int tid, int bi, char* sb) {
    char* Gd = sb + G_OFF + slot * 32768;
    const char* gsrc = (const char*)d_gbfT + (size_t)t * 128;
#pragma unroll
    for (int kk = 0; kk < 8; kk++) {
        int L = tid + kk * 256, row = L >> 3, c = L & 7;
        cpa16(Gd + row * 128 + ((c ^ (row & 7)) << 4), gsrc + (size_t)row * 8192 + c * 16);
    }
    int j = tid >> 2, hh = tid & 3;
    cpa16(sb + RP_OFF + slot * 5120 + j * 80 + hh * 16, d_rp4 + t * 256 + tid);
    if (tid < 32)
        cpa8(sb + ADJ_OFF + slot * 256 + tid * 8, d_adjT + (size_t)(t * NN + bi * 32 + tid) * 2);
}

__global__ __launch_bounds__(256, 1) void k_attn() {
    extern __shared__ char sb[];
    const uint32 sb32 = smem_u32(sb);
    const int tid = threadIdx.x, bi = blockIdx.x;
    const int lane = tid & 31, wid = tid >> 5;
    const int h = wid >> 1, mh = wid & 1;
    const int i4 = lane >> 2, q = lane & 3, jq = q << 1;
    const int r0 = mh * 16 + i4;

    float sl[2], e1[2], e2[2];
#pragma unroll
    for (int r = 0; r < 2; r++) {
        int gi = bi * 32 + r0 + 8 * r;
        sl[r] = d_lpack[gi * 12 + h];
        e1[r] = d_lpack[gi * 12 + 4 + h];
        e2[r] = d_lpack[gi * 12 + 8 + h];
    }
    float C[8][4];
#pragma unroll
    for (int nf = 0; nf < 8; nf++)
#pragma unroll
        for (int qq = 0; qq < 4; qq++) C[nf][qq] = 0.f;
    float dsum[2] = {0.f, 0.f};

    issue_tile(0, 0, tid, bi, sb); CPA_COMMIT();
    issue_tile(1, 1, tid, bi, sb); CPA_COMMIT();

#pragma unroll 1
    for (int t = 0; t < 64; t++) {
        if (t < 63) CPA_WAIT1(); else CPA_WAIT0();
        __syncthreads();
        if (t + 2 < 64) { issue_tile(t + 2, (t + 2) % 3, tid, bi, sb); CPA_COMMIT(); }
        const int slot = t % 3;

        uint32 B[8][8];
        {
            const uint32 gb32 = sb32 + G_OFF + slot * 32768;
            const int fr = h * 64 + (lane & 7), c0 = lane >> 3;
#pragma unroll
            for (int nf = 0; nf < 8; nf++) {
                int f = fr + nf * 8;
                uint32 base = gb32 + f * 128;
                ldmx4(&B[nf][0], base + ((c0 ^ (f & 7)) << 4));
                ldmx4(&B[nf][4], base + (((c0 + 4) ^ (f & 7)) << 4));
            }
        }
        uint32 A[2][8];
        {
            const uint32* sadj = (const uint32*)(sb + ADJ_OFF + slot * 256);
            uint32 aw[2][2];
#pragma unroll
            for (int r = 0; r < 2; r++) {
                aw[r][0] = sadj[(r0 + 8 * r) * 2];
                aw[r][1] = sadj[(r0 + 8 * r) * 2 + 1];
            }
            const char* rpb = sb + RP_OFF + slot * 5120 + h * 16;
#pragma unroll
            for (int c = 0; c < 8; c++) {
                int j0 = jq + (c << 3);
                float4 p0 = *(const float4*)(rpb + j0 * 80);
                float4 p1 = *(const float4*)(rpb + j0 * 80 + 80);
                int half = c >> 2, sh = j0 & 31;
#pragma unroll
                for (int r = 0; r < 2; r++) {
                    float w0 = (sl[r] + p0.x >= 0.f) ? e1[r] * p0.y : e2[r] * p0.z;
                    float w1 = (sl[r] + p1.x >= 0.f) ? e1[r] * p1.y : e2[r] * p1.z;
                    w0 = ((aw[r][half] >> sh) & 1u) ? w0 : 0.f;
                    w1 = ((aw[r][half] >> (sh + 1)) & 1u) ? w1 : 0.f;
                    dsum[r] += w0 + w1;
                    A[r][c] = bf2(w0, w1);
                }
            }
        }
#pragma unroll
        for (int s = 0; s < 4; s++)
#pragma unroll
            for (int nf = 0; nf < 8; nf++)
                mma_bf16(C[nf], A[0][2 * s], A[1][2 * s], A[0][2 * s + 1], A[1][2 * s + 1],
                         B[nf][2 * s], B[nf][2 * s + 1]);
    }

#pragma unroll
    for (int r = 0; r < 2; r++) {
        dsum[r] += __shfl_xor_sync(0xFFFFFFFFu, dsum[r], 1);
        dsum[r] += __shfl_xor_sync(0xFFFFFFFFu, dsum[r], 2);
    }
    float* den = (float*)(sb + DEN_OFF);
    if ((lane & 3) == 0) {
        den[h * 32 + r0] = dsum[0];
        den[h * 32 + r0 + 8] = dsum[1];
    }
    __syncthreads();
    float* inv = (float*)(sb + INV_OFF);
    if (tid < 128) inv[tid] = 1.f / den[tid];
    __syncthreads();
    float* sOut = (float*)(sb + G_OFF);
    {
        float s0 = inv[h * 32 + r0], s8 = inv[h * 32 + r0 + 8];
#pragma unroll
        for (int nf = 0; nf < 8; nf++) {
            int f0 = h * 64 + nf * 8 + jq;
            float* qp = sOut + r0 * 264 + f0;
            qp[0] = C[nf][0] * s0; qp[1] = C[nf][1] * s0;
            float* q8 = sOut + (r0 + 8) * 264 + f0;
            q8[0] = C[nf][2] * s8; q8[1] = C[nf][3] * s8;
        }
    }
    __syncthreads();
#pragma unroll
    for (int n4 = 0; n4 < 8; n4++) {
        float4 v;
        v.x = sOut[(n4 * 4 + 0) * 264 + tid];
        v.y = sOut[(n4 * 4 + 1) * 264 + tid];
        v.z = sOut[(n4 * 4 + 2) * 264 + tid];
        v.w = sOut[(n4 * 4 + 3) * 264 + tid];
        *(float4*)(d_hattT + (size_t)tid * 4096 + bi * 32 + n4 * 4) = v;
    }
}

// ---------------- K3: MLP + partial pool (smem-staged, prefetched) ----------------
// dynamic smem: 256*33 floats (33792B). Phase 1 uses [k*32+row]; phase 2 relaid [k*33+row].
__global__ __launch_bounds__(256) void k_mlp(const float* __restrict__ b1, const float* __restrict__ b2) {
    extern __shared__ float sm[];
    __shared__ float sPart[1024];
    const int tid = threadIdx.x, bi = blockIdx.x;
    const int fg = tid & 63, ig = tid >> 6;
    const int colb = fg * 4;

    // stage Hatt tile: 256 k-rows x 32 floats
#pragma unroll
    for (int c = 0; c < 8; c++) {
        int L = tid + c * 256, k = L >> 3, q = L & 7;
        cpa16(sm + k * 32 + q * 4, d_hattT + (size_t)k * 4096 + bi * 32 + q * 4);
    }
    CPA_COMMIT(); CPA_WAIT0();
    __syncthreads();

    ull acc[16];
#pragma unroll
    for (int q = 0; q < 16; q++) acc[q] = 0ull;
#pragma unroll 1
    for (int k0 = 0; k0 < 256; k0 += 8) {
        ull w01[8], w23[8];
#pragma unroll
        for (int u = 0; u < 8; u++) {
            double2 wd = *(const double2*)(d_W1T + (k0 + u) * 256 + colb);
            w01[u] = dll(wd.x); w23[u] = dll(wd.y);
        }
#pragma unroll
        for (int u = 0; u < 8; u++) {
            const float* ar = sm + (k0 + u) * 32 + ig * 8;
#pragma unroll
            for (int r = 0; r < 8; r++) {
                ull p = pack2(ar[r]);
                acc[r * 2] = fma2(p, w01[u], acc[r * 2]);
                acc[r * 2 + 1] = fma2(p, w23[u], acc[r * 2 + 1]);
            }
        }
    }
    float4 bb = *(const float4*)(b1 + colb);
    float zz[8][4];
#pragma unroll
    for (int r = 0; r < 8; r++) {
        float2 u0 = unpack2(acc[r * 2]), u1 = unpack2(acc[r * 2 + 1]);
        zz[r][0] = fmaxf(u0.x + bb.x, 0.f); zz[r][1] = fmaxf(u0.y + bb.y, 0.f);
        zz[r][2] = fmaxf(u1.x + bb.z, 0.f); zz[r][3] = fmaxf(u1.y + bb.w, 0.f);
    }
    __syncthreads();  // done reading phase-1 layout
    // re-lay layer-1 output: [hid k][row], stride 33
#pragma unroll
    for (int cc = 0; cc < 4; cc++)
#pragma unroll
        for (int r = 0; r < 8; r++)
            sm[(colb + cc) * 33 + ig * 8 + r] = zz[r][cc];
    __syncthreads();

#pragma unroll
    for (int q = 0; q < 16; q++) acc[q] = 0ull;
#pragma unroll 1
    for (int k0 = 0; k0 < 256; k0 += 8) {
        ull w01[8], w23[8];
#pragma unroll
        for (int u = 0; u < 8; u++) {
            double2 wd = *(const double2*)(d_W2T + (k0 + u) * 256 + colb);
            w01[u] = dll(wd.x); w23[u] = dll(wd.y);
        }
#pragma unroll
        for (int u = 0; u < 8; u++) {
            const float* ar = sm + (k0 + u) * 33 + ig * 8;
#pragma unroll
            for (int r = 0; r < 8; r++) {
                ull p = pack2(ar[r]);
                acc[r * 2] = fma2(p, w01[u], acc[r * 2]);
                acc[r * 2 + 1] = fma2(p, w23[u], acc[r * 2 + 1]);
            }
        }
    }
    float4 b2v = *(const float4*)(b2 + colb);
    float pc0 = 8.f * b2v.x, pc1 = 8.f * b2v.y, pc2 = 8.f * b2v.z, pc3 = 8.f * b2v.w;
#pragma unroll
    for (int r = 0; r < 8; r++) {
        float2 u0 = unpack2(acc[r * 2]), u1 = unpack2(acc[r * 2 + 1]);
        pc0 += u0.x; pc1 += u0.y; pc2 += u1.x; pc3 += u1.y;
    }
    *(float4*)(sPart + ig * 256 + colb) = make_float4(pc0, pc1, pc2, pc3);
    __syncthreads();
    d_part[bi * 256 + tid] = sPart[tid] + sPart[256 + tid] + sPart[512 + tid] + sPart[768 + tid];
}

// ---------------- K4 ----------------
__global__ __launch_bounds__(256) void k_final(const float* __restrict__ Wd1, const float* __restrict__ bd1,
                                               const float* __restrict__ Wd2, const float* __restrict__ bd2,
                                               float* __restrict__ out) {
    __shared__ float pooled[256];
    __shared__ float red[256];
    const int o = threadIdx.x;
    float p = 0.f;
    for (int b = 0; b < 128; b++) p += d_part[b * 256 + o];
    pooled[o] = p;
    __syncthreads();
    float accv = 0.f;
    const float* w = Wd1 + o * 256;
#pragma unroll 4
    for (int k = 0; k < 256; k++) accv += w[k] * pooled[k];
    red[o] = fmaxf(accv + bd1[o], 0.f) * Wd2[o];
    __syncthreads();
    for (int s = 128; s > 0; s >>= 1) {
        if (o < s) red[o] += red[o + s];
        __syncthreads();
    }
    if (o == 0) out[0] = red[0] + bd2[0];
}

extern "C" void kernel_launch(void* const* d_in, const int* in_sizes, int n_in,
                              void* d_out, int out_size) {
    const float* nodes = (const float*)d_in[0];
    const int* adj = (const int*)d_in[1];
    const float* Wemb = (const float*)d_in[2];
    const float* Watt = (const float*)d_in[3];
    const float* We1 = (const float*)d_in[4];
    const float* b1 = (const float*)d_in[5];
    const float* We2 = (const float*)d_in[6];
    const float* b2 = (const float*)d_in[7];
    const float* Wd1 = (const float*)d_in[8];
    const float* bd1 = (const float*)d_in[9];
    const float* Wd2 = (const float*)d_in[10];
    const float* bd2 = (const float*)d_in[11];
    float* out = (float*)d_out;

    cudaFuncSetAttribute(k_attn, cudaFuncAttributeMaxDynamicSharedMemorySize, K2_SMEM);

    k_prep<<<640, 256>>>(We1, We2, Wemb);
    k_tnodes<<<dim3(128, 4), dim3(32, 8)>>>(nodes);
    k_adjpack<<<65536, 256>>>(adj);
    k_embed<<<128, 256>>>(Watt);
    k_attn<<<128, 256, K2_SMEM>>>();
    k_mlp<<<128, 256, 33792>>>(b1, b2);
    k_final<<<1, 256>>>(Wd1, bd1, Wd2, bd2, out);
}

// round 15
// speedup vs baseline: 1.4922x; 1.0949x over previous
#include <cuda_runtime.h>
#include <cstdint>
#include <cstddef>

#define NN 4096
typedef unsigned long long ull;
typedef unsigned int uint32;

__device__ unsigned short d_gbfT[256 * NN];  // bf16 g transposed [feat][node]
__device__ float d_lpack[NN * 12];
__device__ float4 d_rp4[NN * 4];             // {sr, exp(sr), exp(.2sr), 0}
__device__ unsigned d_adjT[128 * NN * 2];    // adjacency bits, tile-major
__device__ float d_hattT[256 * NN];
__device__ float d_part[128 * 256];
__device__ float d_W1T[256 * 256];
__device__ float d_W2T[256 * 256];
__device__ float d_WembT[128 * 256];
__device__ float d_nodesT[128 * NN];

__device__ __forceinline__ ull pack2(float x) { ull r; asm("mov.b64 %0, {%1, %1};" : "=l"(r) : "f"(x)); return r; }
__device__ __forceinline__ ull fma2(ull a, ull b, ull c) { ull d; asm("fma.rn.f32x2 %0, %1, %2, %3;" : "=l"(d) : "l"(a), "l"(b), "l"(c)); return d; }
__device__ __forceinline__ float2 unpack2(ull v) { float2 r; asm("mov.b64 {%0, %1}, %2;" : "=f"(r.x), "=f"(r.y) : "l"(v)); return r; }
__device__ __forceinline__ ull dll(double v) { return __double_as_longlong(v); }
__device__ __forceinline__ void cpa16(void* dst, const void* src) {
    unsigned s = (unsigned)__cvta_generic_to_shared(dst);
    asm volatile("cp.async.cg.shared.global [%0], [%1], 16;" ::"r"(s), "l"(src));
}
__device__ __forceinline__ void cpa8(void* dst, const void* src) {
    unsigned s = (unsigned)__cvta_generic_to_shared(dst);
    asm volatile("cp.async.ca.shared.global [%0], [%1], 8;" ::"r"(s), "l"(src));
}
__device__ __forceinline__ unsigned bf2(float lo, float hi) {
    unsigned r; asm("cvt.rn.bf16x2.f32 %0, %1, %2;" : "=r"(r) : "f"(hi), "f"(lo)); return r;
}
__device__ __forceinline__ uint32 smem_u32(const void* p) {
    uint32 a; asm("{ .reg .u64 t; cvta.to.shared.u64 t, %1; cvt.u32.u64 %0, t; }" : "=r"(a) : "l"(p)); return a;
}
#define CPA_COMMIT() asm volatile("cp.async.commit_group;" ::: "memory")
#define CPA_WAIT1() asm volatile("cp.async.wait_group 1;" ::: "memory")
#define CPA_WAIT0() asm volatile("cp.async.wait_group 0;" ::: "memory")

__device__ __forceinline__ void ldmx4(uint32* r, uint32 addr) {
    asm volatile("ldmatrix.sync.aligned.m8n8.x4.shared.b16 {%0,%1,%2,%3}, [%4];"
                 : "=r"(r[0]), "=r"(r[1]), "=r"(r[2]), "=r"(r[3]) : "r"(addr));
}
__device__ __forceinline__ void mma_bf16(float* c, uint32 a0, uint32 a1, uint32 a2, uint32 a3,
                                         uint32 b0, uint32 b1) {
    asm volatile("mma.sync.aligned.m16n8k16.row.col.f32.bf16.bf16.f32 "
                 "{%0,%1,%2,%3},{%4,%5,%6,%7},{%8,%9},{%0,%1,%2,%3};"
                 : "+f"(c[0]), "+f"(c[1]), "+f"(c[2]), "+f"(c[3])
                 : "r"(a0), "r"(a1), "r"(a2), "r"(a3), "r"(b0), "r"(b1));
}

// ---------------- prep: weight transposes ----------------
__global__ __launch_bounds__(256) void k_prep(const float* __restrict__ We1, const float* __restrict__ We2,
                                              const float* __restrict__ Wemb) {
    int i = blockIdx.x * 256 + threadIdx.x;  // 163840
    if (i < 65536) { int k = i >> 8, c = i & 255; d_W1T[i] = We1[c * 256 + k]; }
    else if (i < 131072) { int j = i - 65536, k = j >> 8, c = j & 255; d_W2T[j] = We2[c * 256 + k]; }
    else { int j = i - 131072, k = j >> 8, c = j & 255; d_WembT[j] = Wemb[c * 128 + k]; }
}
__global__ void k_tnodes(const float* __restrict__ nodes) {
    __shared__ float tile[32][33];
    const int bx = blockIdx.x, by = blockIdx.y, tx = threadIdx.x, ty = threadIdx.y;
#pragma unroll
    for (int q = 0; q < 4; q++)
        tile[ty + 8 * q][tx] = nodes[(size_t)(bx * 32 + ty + 8 * q) * 128 + by * 32 + tx];
    __syncthreads();
#pragma unroll
    for (int q = 0; q < 4; q++)
        d_nodesT[(size_t)(by * 32 + ty + 8 * q) * 4096 + bx * 32 + tx] = tile[tx][ty + 8 * q];
}
__global__ __launch_bounds__(256) void k_adjpack(const int* __restrict__ adj) {
    int wg = (blockIdx.x * 256 + threadIdx.x) >> 5, lane = threadIdx.x & 31;
    unsigned v = (adj[(size_t)wg * 32 + lane] != 0) ? 1u : 0u;
    unsigned word = __ballot_sync(0xFFFFFFFFu, v);
    if (lane == 0) {
        int node = wg >> 7, w = wg & 127;
        d_adjT[(size_t)((w >> 1) * NN + node) * 2 + (w & 1)] = word;
    }
}

// ---------------- K1: embed + fused score packs (baseline, unchanged) ----------------
__global__ __launch_bounds__(256) void k_embed(const float* __restrict__ Watt) {
    __shared__ float sA[128 * 32];
    __shared__ float sRed[4096];
    const int tid = threadIdx.x, bi = blockIdx.x;
#pragma unroll
    for (int c = 0; c < 4; c++) {
        int L = tid + c * 256, k = L >> 3, q = L & 7;
        cpa16(sA + k * 32 + q * 4, d_nodesT + (size_t)k * 4096 + bi * 32 + q * 4);
    }
    CPA_COMMIT(); CPA_WAIT0();
    __syncthreads();

    const int fg = tid & 63, ig = tid >> 6;
    const int rowb = bi * 32 + ig * 8, colb = fg * 4;
    ull acc[16];
#pragma unroll
    for (int q = 0; q < 16; q++) acc[q] = 0ull;
#pragma unroll 1
    for (int k0 = 0; k0 < 128; k0 += 8) {
        ull w01[8], w23[8];
#pragma unroll
        for (int u = 0; u < 8; u++) {
            double2 wd = *(const double2*)(d_WembT + (k0 + u) * 256 + colb);
            w01[u] = dll(wd.x); w23[u] = dll(wd.y);
        }
#pragma unroll
        for (int u = 0; u < 8; u++) {
            const float* ar = sA + (k0 + u) * 32 + ig * 8;
#pragma unroll
            for (int r = 0; r < 8; r++) {
                ull p = pack2(ar[r]);
                acc[r * 2] = fma2(p, w01[u], acc[r * 2]);
                acc[r * 2 + 1] = fma2(p, w23[u], acc[r * 2 + 1]);
            }
        }
    }
    float z[8][4];
#pragma unroll
    for (int r = 0; r < 8; r++) {
        float2 u0 = unpack2(acc[r * 2]), u1 = unpack2(acc[r * 2 + 1]);
        z[r][0] = u0.x; z[r][1] = u0.y; z[r][2] = u1.x; z[r][3] = u1.y;
    }
#pragma unroll
    for (int cc = 0; cc < 4; cc++) {
        uint4 q = make_uint4(bf2(z[0][cc], z[1][cc]), bf2(z[2][cc], z[3][cc]),
                             bf2(z[4][cc], z[5][cc]), bf2(z[6][cc], z[7][cc]));
        *(uint4*)((char*)d_gbfT + ((size_t)(colb + cc) * 4096 + rowb) * 2) = q;
    }
    const int h = fg >> 4, fi = fg & 15;
    float4 al = *(const float4*)(Watt + (colb & 63));
    float4 ar4 = *(const float4*)(Watt + 64 + (colb & 63));
#pragma unroll
    for (int r = 0; r < 8; r++) {
        float slp = z[r][0] * al.x + z[r][1] * al.y + z[r][2] * al.z + z[r][3] * al.w;
        float srp = z[r][0] * ar4.x + z[r][1] * ar4.y + z[r][2] * ar4.z + z[r][3] * ar4.w;
        int ri = ig * 8 + r;
        sRed[((ri * 4 + h) * 2 + 0) * 16 + fi] = slp;
        sRed[((ri * 4 + h) * 2 + 1) * 16 + fi] = srp;
    }
    __syncthreads();
    if (tid < 128) {
        int ri = tid >> 2, hh = tid & 3;
        float sl = 0.f, sr = 0.f;
#pragma unroll
        for (int q = 0; q < 16; q++) {
            sl += sRed[((ri * 4 + hh) * 2 + 0) * 16 + q];
            sr += sRed[((ri * 4 + hh) * 2 + 1) * 16 + q];
        }
        int gi = bi * 32 + ri;
        d_lpack[gi * 12 + hh] = sl;
        d_lpack[gi * 12 + 4 + hh] = expf(sl);
        d_lpack[gi * 12 + 8 + hh] = expf(0.2f * sl);
        d_rp4[gi * 4 + hh] = make_float4(sr, expf(sr), expf(0.2f * sr), 0.f);
    }
}

// ---------------- K2: HMMA attention (baseline, unchanged) ----------------
#define G_OFF 0
#define RP_OFF 98304
#define ADJ_OFF 113664
#define DEN_OFF 114432
#define INV_OFF 114944
#define K2_SMEM 115456

__device__ __forceinline__ void issue_tile(int t, int slot, int tid, int bi, char* sb) {
    char* Gd = sb + G_OFF + slot * 32768;
    const char* gsrc = (const char*)d_gbfT + (size_t)t * 128;
#pragma unroll
    for (int kk = 0; kk < 8; kk++) {
        int L = tid + kk * 256, row = L >> 3, c = L & 7;
        cpa16(Gd + row * 128 + ((c ^ (row & 7)) << 4), gsrc + (size_t)row * 8192 + c * 16);
    }
    int j = tid >> 2, hh = tid & 3;
    cpa16(sb + RP_OFF + slot * 5120 + j * 80 + hh * 16, d_rp4 + t * 256 + tid);
    if (tid < 32)
        cpa8(sb + ADJ_OFF + slot * 256 + tid * 8, d_adjT + (size_t)(t * NN + bi * 32 + tid) * 2);
}

__global__ __launch_bounds__(256, 1) void k_attn() {
    extern __shared__ char sb[];
    const uint32 sb32 = smem_u32(sb);
    const int tid = threadIdx.x, bi = blockIdx.x;
    const int lane = tid & 31, wid = tid >> 5;
    const int h = wid >> 1, mh = wid & 1;
    const int i4 = lane >> 2, q = lane & 3, jq = q << 1;
    const int r0 = mh * 16 + i4;

    float sl[2], e1[2], e2[2];
#pragma unroll
    for (int r = 0; r < 2; r++) {
        int gi = bi * 32 + r0 + 8 * r;
        sl[r] = d_lpack[gi * 12 + h];
        e1[r] = d_lpack[gi * 12 + 4 + h];
        e2[r] = d_lpack[gi * 12 + 8 + h];
    }
    float C[8][4];
#pragma unroll
    for (int nf = 0; nf < 8; nf++)
#pragma unroll
        for (int qq = 0; qq < 4; qq++) C[nf][qq] = 0.f;
    float dsum[2] = {0.f, 0.f};

    issue_tile(0, 0, tid, bi, sb); CPA_COMMIT();
    issue_tile(1, 1, tid, bi, sb); CPA_COMMIT();

#pragma unroll 1
    for (int t = 0; t < 64; t++) {
        if (t < 63) CPA_WAIT1(); else CPA_WAIT0();
        __syncthreads();
        if (t + 2 < 64) { issue_tile(t + 2, (t + 2) % 3, tid, bi, sb); CPA_COMMIT(); }
        const int slot = t % 3;

        uint32 B[8][8];
        {
            const uint32 gb32 = sb32 + G_OFF + slot * 32768;
            const int fr = h * 64 + (lane & 7), c0 = lane >> 3;
#pragma unroll
            for (int nf = 0; nf < 8; nf++) {
                int f = fr + nf * 8;
                uint32 base = gb32 + f * 128;
                ldmx4(&B[nf][0], base + ((c0 ^ (f & 7)) << 4));
                ldmx4(&B[nf][4], base + (((c0 + 4) ^ (f & 7)) << 4));
            }
        }
        uint32 A[2][8];
        {
            const uint32* sadj = (const uint32*)(sb + ADJ_OFF + slot * 256);
            uint32 aw[2][2];
#pragma unroll
            for (int r = 0; r < 2; r++) {
                aw[r][0] = sadj[(r0 + 8 * r) * 2];
                aw[r][1] = sadj[(r0 + 8 * r) * 2 + 1];
            }
            const char* rpb = sb + RP_OFF + slot * 5120 + h * 16;
#pragma unroll
            for (int c = 0; c < 8; c++) {
                int j0 = jq + (c << 3);
                float4 p0 = *(const float4*)(rpb + j0 * 80);
                float4 p1 = *(const float4*)(rpb + j0 * 80 + 80);
                int half = c >> 2, sh = j0 & 31;
#pragma unroll
                for (int r = 0; r < 2; r++) {
                    float w0 = (sl[r] + p0.x >= 0.f) ? e1[r] * p0.y : e2[r] * p0.z;
                    float w1 = (sl[r] + p1.x >= 0.f) ? e1[r] * p1.y : e2[r] * p1.z;
                    w0 = ((aw[r][half] >> sh) & 1u) ? w0 : 0.f;
                    w1 = ((aw[r][half] >> (sh + 1)) & 1u) ? w1 : 0.f;
                    dsum[r] += w0 + w1;
                    A[r][c] = bf2(w0, w1);
                }
            }
        }
#pragma unroll
        for (int s = 0; s < 4; s++)
#pragma unroll
            for (int nf = 0; nf < 8; nf++)
                mma_bf16(C[nf], A[0][2 * s], A[1][2 * s], A[0][2 * s + 1], A[1][2 * s + 1],
                         B[nf][2 * s], B[nf][2 * s + 1]);
    }

#pragma unroll
    for (int r = 0; r < 2; r++) {
        dsum[r] += __shfl_xor_sync(0xFFFFFFFFu, dsum[r], 1);
        dsum[r] += __shfl_xor_sync(0xFFFFFFFFu, dsum[r], 2);
    }
    float* den = (float*)(sb + DEN_OFF);
    if ((lane & 3) == 0) {
        den[h * 32 + r0] = dsum[0];
        den[h * 32 + r0 + 8] = dsum[1];
    }
    __syncthreads();
    float* inv = (float*)(sb + INV_OFF);
    if (tid < 128) inv[tid] = 1.f / den[tid];
    __syncthreads();
    float* sOut = (float*)(sb + G_OFF);
    {
        float s0 = inv[h * 32 + r0], s8 = inv[h * 32 + r0 + 8];
#pragma unroll
        for (int nf = 0; nf < 8; nf++) {
            int f0 = h * 64 + nf * 8 + jq;
            float* qp = sOut + r0 * 264 + f0;
            qp[0] = C[nf][0] * s0; qp[1] = C[nf][1] * s0;
            float* q8 = sOut + (r0 + 8) * 264 + f0;
            q8[0] = C[nf][2] * s8; q8[1] = C[nf][3] * s8;
        }
    }
    __syncthreads();
#pragma unroll
    for (int n4 = 0; n4 < 8; n4++) {
        float4 v;
        v.x = sOut[(n4 * 4 + 0) * 264 + tid];
        v.y = sOut[(n4 * 4 + 1) * 264 + tid];
        v.z = sOut[(n4 * 4 + 2) * 264 + tid];
        v.w = sOut[(n4 * 4 + 3) * 264 + tid];
        *(float4*)(d_hattT + (size_t)tid * 4096 + bi * 32 + n4 * 4) = v;
    }
}

// ---------------- K3: MLP + partial pool — split-K, 512 threads ----------------
// dyn smem floats: region A [0,8448) tile [k*32+row] then relaid [hid*33+row];
//                  region B [8448,16640) partial-sum exchange (swizzled)
#define MLP_SMEM 66560

__global__ __launch_bounds__(512) void k_mlp(const float* __restrict__ b1, const float* __restrict__ b2) {
    extern __shared__ float sm[];
    __shared__ float sPart[1024];
    const int tid = threadIdx.x, bi = blockIdx.x;
    const int kg = tid >> 8, tid8 = tid & 255;
    const int fg = tid8 & 63, ig = tid8 >> 6;
    const int colb = fg * 4;
    float* RB = sm + 8448;
    const int sw0 = (tid8 & 7) * 4;  // exchange-buffer swizzle

    // stage Hatt tile: 256 k-rows x 32 floats (512 threads)
#pragma unroll
    for (int c = 0; c < 4; c++) {
        int L = tid + c * 512, k = L >> 3, q = L & 7;
        cpa16(sm + k * 32 + q * 4, d_hattT + (size_t)k * 4096 + bi * 32 + q * 4);
    }
    CPA_COMMIT(); CPA_WAIT0();
    __syncthreads();

    const int kbase = kg * 128;
    ull acc[16];
#pragma unroll
    for (int q = 0; q < 16; q++) acc[q] = 0ull;
#pragma unroll 1
    for (int k0 = 0; k0 < 128; k0 += 8) {
        ull w01[8], w23[8];
#pragma unroll
        for (int u = 0; u < 8; u++) {
            double2 wd = *(const double2*)(d_W1T + (kbase + k0 + u) * 256 + colb);
            w01[u] = dll(wd.x); w23[u] = dll(wd.y);
        }
#pragma unroll
        for (int u = 0; u < 8; u++) {
            const float* ar = sm + (kbase + k0 + u) * 32 + ig * 8;
#pragma unroll
            for (int r = 0; r < 8; r++) {
                ull p = pack2(ar[r]);
                acc[r * 2] = fma2(p, w01[u], acc[r * 2]);
                acc[r * 2 + 1] = fma2(p, w23[u], acc[r * 2 + 1]);
            }
        }
    }
    // combine layer 1 (kg1 -> RB, kg0 adds + bias + relu, relays into region A)
    if (kg == 1) {
#pragma unroll
        for (int r = 0; r < 8; r++) {
            float2 u0 = unpack2(acc[r * 2]), u1 = unpack2(acc[r * 2 + 1]);
            *(float4*)(RB + tid8 * 32 + ((r * 4) ^ sw0)) = make_float4(u0.x, u0.y, u1.x, u1.y);
        }
    }
    __syncthreads();
    if (kg == 0) {
        float4 bb = *(const float4*)(b1 + colb);
        float zz[8][4];
#pragma unroll
        for (int r = 0; r < 8; r++) {
            float2 u0 = unpack2(acc[r * 2]), u1 = unpack2(acc[r * 2 + 1]);
            float4 o = *(const float4*)(RB + tid8 * 32 + ((r * 4) ^ sw0));
            zz[r][0] = fmaxf(u0.x + o.x + bb.x, 0.f);
            zz[r][1] = fmaxf(u0.y + o.y + bb.y, 0.f);
            zz[r][2] = fmaxf(u1.x + o.z + bb.z, 0.f);
            zz[r][3] = fmaxf(u1.y + o.w + bb.w, 0.f);
        }
#pragma unroll
        for (int cc = 0; cc < 4; cc++)
#pragma unroll
            for (int r = 0; r < 8; r++)
                sm[(colb + cc) * 33 + ig * 8 + r] = zz[r][cc];
    }
    __syncthreads();

    // layer 2 (split-K again)
#pragma unroll
    for (int q = 0; q < 16; q++) acc[q] = 0ull;
#pragma unroll 1
    for (int k0 = 0; k0 < 128; k0 += 8) {
        ull w01[8], w23[8];
#pragma unroll
        for (int u = 0; u < 8; u++) {
            double2 wd = *(const double2*)(d_W2T + (kbase + k0 + u) * 256 + colb);
            w01[u] = dll(wd.x); w23[u] = dll(wd.y);
        }
#pragma unroll
        for (int u = 0; u < 8; u++) {
            const float* ar = sm + (kbase + k0 + u) * 33 + ig * 8;
#pragma unroll
            for (int r = 0; r < 8; r++) {
                ull p = pack2(ar[r]);
                acc[r * 2] = fma2(p, w01[u], acc[r * 2]);
                acc[r * 2 + 1] = fma2(p, w23[u], acc[r * 2 + 1]);
            }
        }
    }
    if (kg == 1) {
#pragma unroll
        for (int r = 0; r < 8; r++) {
            float2 u0 = unpack2(acc[r * 2]), u1 = unpack2(acc[r * 2 + 1]);
            *(float4*)(RB + tid8 * 32 + ((r * 4) ^ sw0)) = make_float4(u0.x, u0.y, u1.x, u1.y);
        }
    }
    __syncthreads();
    if (kg == 0) {
        float4 b2v = *(const float4*)(b2 + colb);
        float pc0 = 8.f * b2v.x, pc1 = 8.f * b2v.y, pc2 = 8.f * b2v.z, pc3 = 8.f * b2v.w;
#pragma unroll
        for (int r = 0; r < 8; r++) {
            float2 u0 = unpack2(acc[r * 2]), u1 = unpack2(acc[r * 2 + 1]);
            float4 o = *(const float4*)(RB + tid8 * 32 + ((r * 4) ^ sw0));
            pc0 += u0.x + o.x; pc1 += u0.y + o.y; pc2 += u1.x + o.z; pc3 += u1.y + o.w;
        }
        *(float4*)(sPart + ig * 256 + colb) = make_float4(pc0, pc1, pc2, pc3);
    }
    __syncthreads();
    if (tid < 256)
        d_part[bi * 256 + tid] = sPart[tid] + sPart[256 + tid] + sPart[512 + tid] + sPart[768 + tid];
}

// ---------------- K4 ----------------
__global__ __launch_bounds__(256) void k_final(const float* __restrict__ Wd1, const float* __restrict__ bd1,
                                               const float* __restrict__ Wd2, const float* __restrict__ bd2,
                                               float* __restrict__ out) {
    __shared__ float pooled[256];
    __shared__ float red[256];
    const int o = threadIdx.x;
    float p = 0.f;
    for (int b = 0; b < 128; b++) p += d_part[b * 256 + o];
    pooled[o] = p;
    __syncthreads();
    float accv = 0.f;
    const float* w = Wd1 + o * 256;
#pragma unroll 4
    for (int k = 0; k < 256; k++) accv += w[k] * pooled[k];
    red[o] = fmaxf(accv + bd1[o], 0.f) * Wd2[o];
    __syncthreads();
    for (int s = 128; s > 0; s >>= 1) {
        if (o < s) red[o] += red[o + s];
        __syncthreads();
    }
    if (o == 0) out[0] = red[0] + bd2[0];
}

extern "C" void kernel_launch(void* const* d_in, const int* in_sizes, int n_in,
                              void* d_out, int out_size) {
    const float* nodes = (const float*)d_in[0];
    const int* adj = (const int*)d_in[1];
    const float* Wemb = (const float*)d_in[2];
    const float* Watt = (const float*)d_in[3];
    const float* We1 = (const float*)d_in[4];
    const float* b1 = (const float*)d_in[5];
    const float* We2 = (const float*)d_in[6];
    const float* b2 = (const float*)d_in[7];
    const float* Wd1 = (const float*)d_in[8];
    const float* bd1 = (const float*)d_in[9];
    const float* Wd2 = (const float*)d_in[10];
    const float* bd2 = (const float*)d_in[11];
    float* out = (float*)d_out;

    cudaFuncSetAttribute(k_attn, cudaFuncAttributeMaxDynamicSharedMemorySize, K2_SMEM);
    cudaFuncSetAttribute(k_mlp, cudaFuncAttributeMaxDynamicSharedMemorySize, MLP_SMEM);

    k_prep<<<640, 256>>>(We1, We2, Wemb);
    k_tnodes<<<dim3(128, 4), dim3(32, 8)>>>(nodes);
    k_adjpack<<<65536, 256>>>(adj);
    k_embed<<<128, 256>>>(Watt);
    k_attn<<<128, 256, K2_SMEM>>>();
    k_mlp<<<128, 512, MLP_SMEM>>>(b1, b2);
    k_final<<<1, 256>>>(Wd1, bd1, Wd2, bd2, out);
}